// round 16
// baseline (speedup 1.0000x reference)
#include <cuda_runtime.h>
#include <cuda.h>
#include <cuda_fp16.h>
#include <cstdint>
#include <cstddef>

#define NTOK   32768      // B*T
#define KDIM   1024
#define BM     128
#define BN     128
#define BKB    64         // K per stage
#define NITER  (KDIM/BKB) // 16

// per-stage smem: A 16K + B 16K = 32K; 3-stage ring = 96K (+1K align) -> 2 CTAs/SM
#define A_BYTES   (BM*128)
#define B_BYTES   (BN*128)
#define ST_BYTES  (A_BYTES + B_BYTES)
#define DSMEM_BYTES (3*ST_BYTES + 1024)

// ---------------- scratch (device globals) ----------------
__device__ __half g_l16[NTOK*1024], g_m16[NTOK*1024];                 // fp16 activations
__device__ __half g_pl [(size_t)NTOK*3072], g_pm [(size_t)NTOK*3072]; // fused q|kv projections
__device__ __half g_al [NTOK*1024], g_am [NTOK*1024];                 // attn outputs

__device__ __half g_wl_cat[3072*1024];   // [q | kv] liquid weights, [N,K]
__device__ __half g_wm_cat[3072*1024];   // [q | kv] mamba weights
__device__ __half g_wlo [1024*1024];
__device__ __half g_wmo [1024*1024];
__device__ float  g_bias_l[3072], g_bias_m[3072];

// ---------------- PTX helpers ----------------
__device__ __forceinline__ unsigned smem_u32(const void* p) {
    unsigned r;
    asm("{ .reg .u64 t; cvta.to.shared.u64 t, %1; cvt.u32.u64 %0, t; }" : "=r"(r) : "l"(p));
    return r;
}
__device__ __forceinline__ void ldsm_x4(uint32_t* r, unsigned addr) {
    asm volatile("ldmatrix.sync.aligned.m8n8.x4.shared.b16 {%0,%1,%2,%3}, [%4];"
        : "=r"(r[0]), "=r"(r[1]), "=r"(r[2]), "=r"(r[3]) : "r"(addr));
}
// fp16-accumulate MMA: D(f16x2 x2) = A*B + D
__device__ __forceinline__ void mma_f16acc(uint32_t* d, const uint32_t* a,
                                           uint32_t b0, uint32_t b1) {
    asm volatile(
        "mma.sync.aligned.m16n8k16.row.col.f16.f16.f16.f16 "
        "{%0,%1}, {%2,%3,%4,%5}, {%6,%7}, {%0,%1};"
        : "+r"(d[0]), "+r"(d[1])
        : "r"(a[0]), "r"(a[1]), "r"(a[2]), "r"(a[3]), "r"(b0), "r"(b1));
}

#define MBAR_INIT(addr, cnt) \
    asm volatile("mbarrier.init.shared.b64 [%0], %1;" :: "r"(addr), "r"(cnt) : "memory")
#define MBAR_EXPECT_TX(addr, tx) \
    asm volatile("mbarrier.arrive.expect_tx.shared.b64 _, [%0], %1;" :: "r"(addr), "r"(tx) : "memory")
#define MBAR_ARRIVE(addr) \
    asm volatile("mbarrier.arrive.shared.b64 _, [%0];" :: "r"(addr) : "memory")

__device__ __forceinline__ void mbar_wait(unsigned addr, unsigned parity) {
    asm volatile(
        "{\n\t.reg .pred P;\n\t"
        "WL_%=:\n\t"
        "mbarrier.try_wait.parity.acquire.cta.shared::cta.b64 P, [%0], %1;\n\t"
        "@!P bra WL_%=;\n\t"
        "}" :: "r"(addr), "r"(parity) : "memory");
}

__device__ __forceinline__ void tma_2d(unsigned smem, const void* map,
                                       int cx, int cy, unsigned mbar) {
    asm volatile(
        "cp.async.bulk.tensor.2d.shared::cta.global.tile.mbarrier::complete_tx::bytes "
        "[%0], [%1, {%2, %3}], [%4];"
        :: "r"(smem), "l"(map), "r"(cx), "r"(cy), "r"(mbar) : "memory");
}

// ---------------- fused-pair fp16 MMA GEMM with TMA + full/empty mbarrier ring
// Dual fp16 accumulator banks (K split at 512) summed in fp32 in the epilogue.
// Mainloop FULLY UNROLLED: stage index, parity and acc bank are compile-time.
struct GPair {
    const float* bias[2];
    const float* res[2];
    void*        C[2];
};
struct TMaps { CUtensorMap a[2]; CUtensorMap b[2]; };

template<bool OUT_HALF>
__global__ __launch_bounds__(256, 2)
void gemm_f16(const __grid_constant__ TMaps maps, GPair p, int N, int gn)
{
    extern __shared__ char dsm_raw[];
    __shared__ __align__(8) uint64_t s_full[3];
    __shared__ __align__(8) uint64_t s_empty[3];

    const int z = blockIdx.z;
    const float* __restrict__ bias = p.bias[z];
    const float* __restrict__ res  = p.res[z];
    void* Cout = p.C[z];

    const int tid = threadIdx.x;
    const int l   = tid & 31;
    const int w   = tid >> 5;
    const int wm  = w >> 2;   // 0..1 (64-row slab)
    const int wn  = w & 3;    // 0..3 (32-col slab)

    // GROUP_M=16 rasterization
    const int gid   = blockIdx.x;
    const int width = 16 * gn;
    const int group = gid / width;
    const int inner = gid - group * width;
    const int m0 = (group * 16 + (inner & 15)) * BM;
    const int n0 = (inner >> 4) * BN;

    const unsigned sbase = (smem_u32(dsm_raw) + 1023u) & ~1023u;   // SW128 atom alignment
    const unsigned fb0 = smem_u32(&s_full[0]);
    const unsigned eb0 = smem_u32(&s_empty[0]);

    if (tid == 0) {
        #pragma unroll
        for (int i = 0; i < 3; i++) {
            MBAR_INIT(fb0 + i*8, 1);   // TMA tx-based
            MBAR_INIT(eb0 + i*8, 8);   // one arrive per warp
        }
        asm volatile("fence.proxy.async.shared::cta;" ::: "memory");
    }
    __syncthreads();

    auto issue = [&](int it) {
        const int s  = it % 3;
        const int k0 = (it & (NITER - 1)) * BKB;
        const unsigned st = sbase + (unsigned)s * ST_BYTES;
        const unsigned mb = fb0 + (unsigned)s * 8;
        MBAR_EXPECT_TX(mb, (unsigned)ST_BYTES);
        tma_2d(st,           &maps.a[z], k0, m0, mb);
        tma_2d(st + A_BYTES, &maps.b[z], k0, n0, mb);
    };

    if (tid == 0) { issue(0); issue(1); issue(2); }

    // ---- hoisted, iteration-invariant LDSM addressing ----
    const int rowA = wm * 64 + (l & 15);
    const int cA   = l >> 4;
    const int xA   = rowA & 7;
    const int rowB = wn * 32 + ((l >> 3) & 1) * 8 + (l & 7);
    const int cB   = l >> 4;
    const int xB   = rowB & 7;

    unsigned aoff[4][4], boff[4][2];
    #pragma unroll
    for (int ks = 0; ks < 4; ks++) {
        const unsigned ka = (unsigned)(((ks*2 + cA) ^ xA) << 4);
        const unsigned kb = (unsigned)(((ks*2 + cB) ^ xB) << 4);
        #pragma unroll
        for (int mi = 0; mi < 4; mi++)
            aoff[ks][mi] = (unsigned)(rowA*128 + mi*2048) + ka;
        #pragma unroll
        for (int bj = 0; bj < 2; bj++)
            boff[ks][bj] = (unsigned)(rowB*128 + bj*2048) + kb;
    }

    // dual fp16 accumulator banks: [chunk][mi][ni][2 regs] (statically indexed)
    uint32_t acc[2][4][4][2];
    #pragma unroll
    for (int c = 0; c < 2; c++)
        #pragma unroll
        for (int mi = 0; mi < 4; mi++)
            #pragma unroll
            for (int ni = 0; ni < 4; ni++) {
                acc[c][mi][ni][0] = 0u;
                acc[c][mi][ni][1] = 0u;
            }

    #pragma unroll
    for (int s = 0; s < NITER; ++s) {
        const int stg = s % 3;                         // compile-time
        const unsigned par = (unsigned)((s / 3) & 1);  // compile-time
        const int ch  = s >> 3;                        // compile-time bank select

        // consumer: wait for this stage's TMA completion
        mbar_wait(fb0 + (unsigned)(stg * 8), par);

        const unsigned st = sbase + (unsigned)(stg * ST_BYTES);
        const unsigned sA = st;
        const unsigned sB = st + A_BYTES;

        #pragma unroll
        for (int ks = 0; ks < 4; ks++) {
            uint32_t a[4][4], b[2][4];
            #pragma unroll
            for (int mi = 0; mi < 4; mi++)
                ldsm_x4(a[mi], sA + aoff[ks][mi]);
            #pragma unroll
            for (int bj = 0; bj < 2; bj++)
                ldsm_x4(b[bj], sB + boff[ks][bj]);
            #pragma unroll
            for (int mi = 0; mi < 4; mi++)
                #pragma unroll
                for (int ni = 0; ni < 4; ni++) {
                    const int bj = ni >> 1, sel = ni & 1;
                    mma_f16acc(acc[ch][mi][ni], a[mi], b[bj][sel], b[bj][sel+2]);
                }
        }

        // release: one lane per warp arrives (all LDSMs for this stage done)
        if (l == 0) MBAR_ARRIVE(eb0 + (unsigned)(stg * 8));

        // producer: thread 0 (after its own arrival) waits for all 8 warps,
        // then refills this slot with chunk s+3.
        if (s + 3 < NITER) {
            if (tid == 0) {
                mbar_wait(eb0 + (unsigned)(stg * 8), par);
                issue(s + 3);
            }
        }
    }

    // epilogue: fp32 combine of both fp16 banks
    const int tr = l >> 2;
    const int tc = (l & 3) * 2;
    #pragma unroll
    for (int ni = 0; ni < 4; ni++) {
        const int col = n0 + wn*32 + ni*8 + tc;
        const float2 bv = *(const float2*)(bias + col);
        #pragma unroll
        for (int mi = 0; mi < 4; mi++) {
            const int row = m0 + wm*64 + mi*16 + tr;
            const float2 p0 = __half22float2(*(const __half2*)&acc[0][mi][ni][0]);
            const float2 q0 = __half22float2(*(const __half2*)&acc[1][mi][ni][0]);
            const float2 p1 = __half22float2(*(const __half2*)&acc[0][mi][ni][1]);
            const float2 q1 = __half22float2(*(const __half2*)&acc[1][mi][ni][1]);
            float x0 = p0.x + q0.x + bv.x, y0 = p0.y + q0.y + bv.y;
            float x1 = p1.x + q1.x + bv.x, y1 = p1.y + q1.y + bv.y;
            if (OUT_HALF) {
                __half2* C = (__half2*)Cout;
                C[((size_t)row     * N + col) >> 1] = __floats2half2_rn(x0, y0);
                C[((size_t)(row+8) * N + col) >> 1] = __floats2half2_rn(x1, y1);
            } else {
                float* C = (float*)Cout;
                const float2 r0 = *(const float2*)(res + (size_t)row * N + col);
                const float2 r1 = *(const float2*)(res + (size_t)(row+8) * N + col);
                *(float2*)(C + (size_t)row     * N + col) = make_float2(x0 + r0.x, y0 + r0.y);
                *(float2*)(C + (size_t)(row+8) * N + col) = make_float2(x1 + r1.x, y1 + r1.y);
            }
        }
    }
}

// ---------------- fused activation convert (grid-stride, both tensors) --------
__global__ __launch_bounds__(256)
void cvt_act2(const float4* __restrict__ x0, uint2* __restrict__ o0,
              const float4* __restrict__ x1, uint2* __restrict__ o1, int n4)
{
    const int stride = gridDim.x * 256;
    for (int i = blockIdx.x * 256 + threadIdx.x; i < n4; i += stride) {
        float4 v = x0[i];
        __half2 a = __floats2half2_rn(v.x, v.y);
        __half2 b = __floats2half2_rn(v.z, v.w);
        o0[i] = make_uint2(*(uint32_t*)&a, *(uint32_t*)&b);
        v = x1[i];
        a = __floats2half2_rn(v.x, v.y);
        b = __floats2half2_rn(v.z, v.w);
        o1[i] = make_uint2(*(uint32_t*)&a, *(uint32_t*)&b);
    }
}

// ---------------- fused weight transpose+convert (6 weights, one launch) ------
struct TW { const float* W; __half* T; int N; };
struct TW6 { TW t[6]; };

__global__ __launch_bounds__(256)
void transpose_all(TW6 p)
{
    const TW e = p.t[blockIdx.z];
    const int bx = blockIdx.x * 32;     // N offset
    if (bx >= e.N) return;
    const int by = blockIdx.y * 32;     // K offset
    __shared__ float t[32][33];
    const int tx = threadIdx.x & 31, ty = threadIdx.x >> 5;
    #pragma unroll
    for (int i = 0; i < 32; i += 8)
        t[ty + i][tx] = e.W[(size_t)(by + ty + i) * e.N + bx + tx];
    __syncthreads();
    #pragma unroll
    for (int i = 0; i < 32; i += 8)
        e.T[(size_t)(bx + ty + i) * KDIM + by + tx] = __float2half(t[tx][ty + i]);
}

// ---------------- bias concat ----------------
__global__ __launch_bounds__(256)
void concat_bias(const float* blq, const float* blkv, const float* bmq, const float* bmkv)
{
    const int i = blockIdx.x * 256 + threadIdx.x;   // 0..3071
    if (i < 1024) { g_bias_l[i] = blq[i];       g_bias_m[i] = bmq[i]; }
    else          { g_bias_l[i] = blkv[i-1024]; g_bias_m[i] = bmkv[i-1024]; }
}

// ---------------- per-token 8x8 cross-head attention: 2 tokens / block --------
// proj layout: [tok][3072] = [q(1024) | kv(2048)]
// mod0: q from pl, kv from pm ; mod1: q from pm, kv from pl
__global__ __launch_bounds__(256)
void attn_kernel()
{
    const int tok0 = blockIdx.x * 2;
    const int tid  = threadIdx.x;

    __shared__ __half sq [2][2][1024];
    __shared__ __half skv[2][2][8*264];
    __shared__ float  swt[2][2][8][8];

    {
        #pragma unroll
        for (int i = 0; i < 2; i++) {
            const int idx = tid + i*256;         // 0..511
            const int t = idx >> 8, rest = idx & 255;
            const int mod = rest >> 7, r = rest & 127;
            const __half* src = (mod ? g_pm : g_pl) + (size_t)(tok0 + t) * 3072;
            ((uint4*)sq[t][mod])[r] = ((const uint4*)src)[r];
        }
        #pragma unroll
        for (int i = 0; i < 4; i++) {
            const int idx = tid + i*256;         // 0..1023
            const int t = idx >> 9, rest = idx & 511;
            const int mod = rest >> 8, o8 = rest & 255;
            const int g = o8 >> 5, c = o8 & 31;
            const __half* src = (mod ? g_pl : g_pm) + (size_t)(tok0 + t) * 3072 + 1024;
            *(uint4*)&skv[t][mod][g*264 + c*8] = ((const uint4*)src)[o8];
        }
    }
    __syncthreads();

    {
        const int t = tid >> 7, mod = (tid >> 6) & 1, h = (tid >> 3) & 7, g = tid & 7;
        const __half2* q = (const __half2*)&sq [t][mod][h*128];
        const __half2* k = (const __half2*)&skv[t][mod][g*264];
        float s = 0.f;
        #pragma unroll
        for (int d = 0; d < 64; d++) {
            const float2 qf = __half22float2(q[d]);
            const float2 kf = __half22float2(k[d]);
            s += qf.x * kf.x + qf.y * kf.y;
        }
        swt[t][mod][h][g] = s * 0.08838834764831845f;   // 1/sqrt(128)
    }
    __syncthreads();

    if (tid < 32) {
        const int t = tid >> 4, mod = (tid >> 3) & 1, h = tid & 7;
        float mx = -1e30f;
        #pragma unroll
        for (int g = 0; g < 8; g++) mx = fmaxf(mx, swt[t][mod][h][g]);
        float e[8], sum = 0.f;
        #pragma unroll
        for (int g = 0; g < 8; g++) { e[g] = __expf(swt[t][mod][h][g] - mx); sum += e[g]; }
        const float inv = 1.0f / sum;
        #pragma unroll
        for (int g = 0; g < 8; g++) swt[t][mod][h][g] = e[g] * inv;
    }
    __syncthreads();

    #pragma unroll
    for (int j = 0; j < 2; j++) {
        const int idx = tid + j*256;
        const int t = idx >> 8, rest = idx & 255;
        const int mod = rest >> 7, h = (rest >> 4) & 7, db = (rest & 15) * 8;
        float o[8] = {0,0,0,0,0,0,0,0};
        #pragma unroll
        for (int g = 0; g < 8; g++) {
            const float wv = swt[t][mod][h][g];
            const __half2* v = (const __half2*)&skv[t][mod][g*264 + 128 + db];
            #pragma unroll
            for (int jj = 0; jj < 4; jj++) {
                const float2 vf = __half22float2(v[jj]);
                o[2*jj]   += wv * vf.x;
                o[2*jj+1] += wv * vf.y;
            }
        }
        __half hb[8];
        #pragma unroll
        for (int i = 0; i < 8; i++) hb[i] = __float2half(o[i]);
        __half* out = (mod == 0 ? g_al : g_am) + (size_t)(tok0 + t) * 1024 + h*128 + db;
        *(uint4*)out = *(uint4*)hb;
    }
}

// ---------------- launch ----------------
typedef CUresult (*EncFn)(CUtensorMap*, CUtensorMapDataType, cuuint32_t, void*,
                          const cuuint64_t*, const cuuint64_t*, const cuuint32_t*,
                          const cuuint32_t*, CUtensorMapInterleave, CUtensorMapSwizzle,
                          CUtensorMapL2promotion, CUtensorMapFloatOOBfill);

extern "C" void kernel_launch(void* const* d_in, const int* in_sizes, int n_in,
                              void* d_out, int out_size)
{
    (void)in_sizes; (void)n_in; (void)out_size;
    const float* liquid = (const float*)d_in[0];
    const float* mamba  = (const float*)d_in[1];
    const float* Wlq  = (const float*)d_in[2];
    const float* blq  = (const float*)d_in[3];
    const float* Wmkv = (const float*)d_in[4];
    const float* bmkv = (const float*)d_in[5];
    const float* Wmq  = (const float*)d_in[6];
    const float* bmq  = (const float*)d_in[7];
    const float* Wlkv = (const float*)d_in[8];
    const float* blkv = (const float*)d_in[9];
    const float* Wlo  = (const float*)d_in[10];
    const float* blo  = (const float*)d_in[11];
    const float* Wmo  = (const float*)d_in[12];
    const float* bmo  = (const float*)d_in[13];

    float* out_l = (float*)d_out;
    float* out_m = out_l + (size_t)NTOK * 1024;

    #define SYM(p, s) void* p; cudaGetSymbolAddress(&p, s)
    SYM(l16, g_l16); SYM(m16, g_m16);
    SYM(pl, g_pl);   SYM(pm, g_pm);
    SYM(al, g_al);   SYM(am, g_am);
    SYM(wl_cat, g_wl_cat); SYM(wm_cat, g_wm_cat);
    SYM(wlo, g_wlo); SYM(wmo, g_wmo);
    SYM(bias_l, g_bias_l); SYM(bias_m, g_bias_m);
    #undef SYM

    // driver entry point for tensor-map encoding (no libcuda link needed)
    void* enc_raw = nullptr;
    cudaDriverEntryPointQueryResult qres;
    cudaGetDriverEntryPointByVersion("cuTensorMapEncodeTiled", &enc_raw, 12000,
                                     cudaEnableDefault, &qres);
    EncFn enc = (EncFn)enc_raw;

    auto mk = [&](CUtensorMap* m, void* ptr, unsigned long long rows) {
        cuuint64_t dims[2]    = {1024ull, rows};
        cuuint64_t strides[1] = {2048ull};          // row pitch in bytes
        cuuint32_t box[2]     = {64u, 128u};        // 64 fp16 = 128B (SW128 atom), 128 rows
        cuuint32_t es[2]      = {1u, 1u};
        enc(m, CU_TENSOR_MAP_DATA_TYPE_FLOAT16, 2, ptr, dims, strides, box, es,
            CU_TENSOR_MAP_INTERLEAVE_NONE, CU_TENSOR_MAP_SWIZZLE_128B,
            CU_TENSOR_MAP_L2_PROMOTION_L2_128B, CU_TENSOR_MAP_FLOAT_OOB_FILL_NONE);
    };

    cudaFuncSetAttribute(gemm_f16<true>,  cudaFuncAttributeMaxDynamicSharedMemorySize, DSMEM_BYTES);
    cudaFuncSetAttribute(gemm_f16<false>, cudaFuncAttributeMaxDynamicSharedMemorySize, DSMEM_BYTES);

    // stage 0: fused prep
    cvt_act2<<<2048, 256>>>((const float4*)liquid, (uint2*)l16,
                            (const float4*)mamba,  (uint2*)m16, NTOK*1024/4);
    TW6 tw;
    tw.t[0] = {Wlq,  (__half*)wl_cat,                      1024};
    tw.t[1] = {Wlkv, (__half*)wl_cat + (size_t)1024*KDIM,  2048};
    tw.t[2] = {Wmq,  (__half*)wm_cat,                      1024};
    tw.t[3] = {Wmkv, (__half*)wm_cat + (size_t)1024*KDIM,  2048};
    tw.t[4] = {Wlo,  (__half*)wlo,                         1024};
    tw.t[5] = {Wmo,  (__half*)wmo,                         1024};
    transpose_all<<<dim3(64, 32, 6), 256>>>(tw);
    concat_bias<<<12, 256>>>(blq, blkv, bmq, bmkv);

    // stage 1: fused q|kv projections, both modalities in ONE launch (grid.z=2)
    const int gm = NTOK / BM;  // 256
    {
        TMaps maps;
        mk(&maps.a[0], l16, NTOK);      mk(&maps.a[1], m16, NTOK);
        mk(&maps.b[0], wl_cat, 3072);   mk(&maps.b[1], wm_cat, 3072);
        GPair p;
        p.bias[0] = (const float*)bias_l; p.bias[1] = (const float*)bias_m;
        p.res[0] = nullptr;               p.res[1] = nullptr;
        p.C[0]  = pl;                     p.C[1]  = pm;
        gemm_f16<true><<<dim3(gm * (3072/BN), 1, 2), 256, DSMEM_BYTES>>>(maps, p, 3072, 3072/BN);
    }

    // stage 2: per-token attention (2 tokens per block)
    attn_kernel<<<NTOK/2, 256>>>();

    // stage 3: output projections + residual, both modalities in ONE launch
    {
        TMaps maps;
        mk(&maps.a[0], al, NTOK);    mk(&maps.a[1], am, NTOK);
        mk(&maps.b[0], wlo, 1024);   mk(&maps.b[1], wmo, 1024);
        GPair p;
        p.bias[0] = blo;   p.bias[1] = bmo;
        p.res[0] = liquid; p.res[1] = mamba;
        p.C[0]  = out_l;   p.C[1]  = out_m;
        gemm_f16<false><<<dim3(gm * (1024/BN), 1, 2), 256, DSMEM_BYTES>>>(maps, p, 1024, 1024/BN);
    }
}

// round 17
// speedup vs baseline: 1.0149x; 1.0149x over previous
#include <cuda_runtime.h>
#include <cuda.h>
#include <cuda_fp16.h>
#include <cstdint>
#include <cstddef>

#define NTOK   32768      // B*T
#define KDIM   1024
#define BM     128
#define BN     256
#define BKB    64         // K per stage
#define NITER  (KDIM/BKB) // 16

// per-stage smem: A 16K + B 32K = 48K; 2-stage ring = 96K (+1K align) -> 2 CTAs/SM
#define A_BYTES   (BM*128)
#define B_BYTES   (BN*128)
#define ST_BYTES  (A_BYTES + B_BYTES)
#define DSMEM_BYTES (2*ST_BYTES + 1024)

// ---------------- scratch (device globals) ----------------
__device__ __half g_l16[NTOK*1024], g_m16[NTOK*1024];                 // fp16 activations
__device__ __half g_pl [(size_t)NTOK*3072], g_pm [(size_t)NTOK*3072]; // fused q|kv projections
__device__ __half g_al [NTOK*1024], g_am [NTOK*1024];                 // attn outputs

__device__ __half g_wl_cat[3072*1024];   // [q | kv] liquid weights, [N,K]
__device__ __half g_wm_cat[3072*1024];   // [q | kv] mamba weights
__device__ __half g_wlo [1024*1024];
__device__ __half g_wmo [1024*1024];
__device__ float  g_bias_l[3072], g_bias_m[3072];

// ---------------- PTX helpers ----------------
__device__ __forceinline__ unsigned smem_u32(const void* p) {
    unsigned r;
    asm("{ .reg .u64 t; cvta.to.shared.u64 t, %1; cvt.u32.u64 %0, t; }" : "=r"(r) : "l"(p));
    return r;
}
__device__ __forceinline__ void ldsm_x4(uint32_t* r, unsigned addr) {
    asm volatile("ldmatrix.sync.aligned.m8n8.x4.shared.b16 {%0,%1,%2,%3}, [%4];"
        : "=r"(r[0]), "=r"(r[1]), "=r"(r[2]), "=r"(r[3]) : "r"(addr));
}
// fp16-accumulate MMA: D(f16x2 x2) = A*B + D
__device__ __forceinline__ void mma_f16acc(uint32_t* d, const uint32_t* a,
                                           uint32_t b0, uint32_t b1) {
    asm volatile(
        "mma.sync.aligned.m16n8k16.row.col.f16.f16.f16.f16 "
        "{%0,%1}, {%2,%3,%4,%5}, {%6,%7}, {%0,%1};"
        : "+r"(d[0]), "+r"(d[1])
        : "r"(a[0]), "r"(a[1]), "r"(a[2]), "r"(a[3]), "r"(b0), "r"(b1));
}

#define MBAR_INIT(addr, cnt) \
    asm volatile("mbarrier.init.shared.b64 [%0], %1;" :: "r"(addr), "r"(cnt) : "memory")
#define MBAR_EXPECT_TX(addr, tx) \
    asm volatile("mbarrier.arrive.expect_tx.shared.b64 _, [%0], %1;" :: "r"(addr), "r"(tx) : "memory")
#define MBAR_ARRIVE(addr) \
    asm volatile("mbarrier.arrive.shared.b64 _, [%0];" :: "r"(addr) : "memory")

__device__ __forceinline__ void mbar_wait(unsigned addr, unsigned parity) {
    asm volatile(
        "{\n\t.reg .pred P;\n\t"
        "WL_%=:\n\t"
        "mbarrier.try_wait.parity.acquire.cta.shared::cta.b64 P, [%0], %1;\n\t"
        "@!P bra WL_%=;\n\t"
        "}" :: "r"(addr), "r"(parity) : "memory");
}

__device__ __forceinline__ void tma_2d(unsigned smem, const void* map,
                                       int cx, int cy, unsigned mbar) {
    asm volatile(
        "cp.async.bulk.tensor.2d.shared::cta.global.tile.mbarrier::complete_tx::bytes "
        "[%0], [%1, {%2, %3}], [%4];"
        :: "r"(smem), "l"(map), "r"(cx), "r"(cy), "r"(mbar) : "memory");
}

// ---------------- fused-pair fp16 MMA GEMM: 64x64 warp tile, fp16 acc --------
// 8 warps (2 x 4), warp tile 64x64, 2-stage TMA ring, single fp16 acc bank.
struct GPair {
    const float* bias[2];
    const float* res[2];
    void*        C[2];
};
struct TMaps { CUtensorMap a[2]; CUtensorMap b[2]; };

template<bool OUT_HALF>
__global__ __launch_bounds__(256, 2)
void gemm_f16(const __grid_constant__ TMaps maps, GPair p, int N, int gn)
{
    extern __shared__ char dsm_raw[];
    __shared__ __align__(8) uint64_t s_full[2];
    __shared__ __align__(8) uint64_t s_empty[2];

    const int z = blockIdx.z;
    const float* __restrict__ bias = p.bias[z];
    const float* __restrict__ res  = p.res[z];
    void* Cout = p.C[z];

    const int tid = threadIdx.x;
    const int l   = tid & 31;
    const int w   = tid >> 5;
    const int wm  = w >> 2;   // 0..1 (64-row slab)
    const int wn  = w & 3;    // 0..3 (64-col slab)

    // GROUP_M=16 rasterization
    const int gid   = blockIdx.x;
    const int width = 16 * gn;
    const int group = gid / width;
    const int inner = gid - group * width;
    const int m0 = (group * 16 + (inner & 15)) * BM;
    const int n0 = (inner >> 4) * BN;

    const unsigned sbase = (smem_u32(dsm_raw) + 1023u) & ~1023u;   // SW128 atom alignment
    const unsigned fb0 = smem_u32(&s_full[0]);
    const unsigned eb0 = smem_u32(&s_empty[0]);

    if (tid == 0) {
        #pragma unroll
        for (int i = 0; i < 2; i++) {
            MBAR_INIT(fb0 + i*8, 1);   // TMA tx-based
            MBAR_INIT(eb0 + i*8, 8);   // one arrive per warp
        }
        asm volatile("fence.proxy.async.shared::cta;" ::: "memory");
    }
    __syncthreads();

    auto issue = [&](int it) {
        const int s  = it & 1;
        const int k0 = (it & (NITER - 1)) * BKB;
        const unsigned st = sbase + (unsigned)s * ST_BYTES;
        const unsigned mb = fb0 + (unsigned)s * 8;
        MBAR_EXPECT_TX(mb, (unsigned)ST_BYTES);
        tma_2d(st,           &maps.a[z], k0, m0, mb);
        tma_2d(st + A_BYTES, &maps.b[z], k0, n0, mb);
    };

    if (tid == 0) { issue(0); issue(1); }

    // ---- LDSM addressing (base rows; per-ks XOR computed inline) ----
    const int rowA = wm * 64 + (l & 15);
    const int cA   = l >> 4;
    const int xA   = rowA & 7;
    const unsigned abase = (unsigned)(rowA * 128);
    const int rowB = wn * 64 + ((l >> 3) & 1) * 8 + (l & 7);
    const int cB   = l >> 4;
    const int xB   = rowB & 7;
    const unsigned bbase = (unsigned)(rowB * 128);

    // single fp16 accumulator bank: [mi][ni][2 regs] = 64 regs
    uint32_t acc[4][8][2];
    #pragma unroll
    for (int mi = 0; mi < 4; mi++)
        #pragma unroll
        for (int ni = 0; ni < 8; ni++) {
            acc[mi][ni][0] = 0u;
            acc[mi][ni][1] = 0u;
        }

    for (int s = 0; s < NITER; ++s) {
        const int stg = s & 1;
        const unsigned par = (unsigned)((s >> 1) & 1);

        // consumer: wait for this stage's TMA completion
        mbar_wait(fb0 + (unsigned)stg * 8, par);

        const unsigned st = sbase + (unsigned)stg * ST_BYTES;
        const unsigned sA = st;
        const unsigned sB = st + A_BYTES;

        #pragma unroll
        for (int ks = 0; ks < 4; ks++) {
            uint32_t a[4][4], b[4][4];
            const unsigned ka = (unsigned)(((ks*2 + cA) ^ xA) << 4);
            const unsigned kb = (unsigned)(((ks*2 + cB) ^ xB) << 4);
            #pragma unroll
            for (int mi = 0; mi < 4; mi++)
                ldsm_x4(a[mi], sA + abase + (unsigned)(mi*2048) + ka);
            #pragma unroll
            for (int bj = 0; bj < 4; bj++)
                ldsm_x4(b[bj], sB + bbase + (unsigned)(bj*2048) + kb);
            #pragma unroll
            for (int mi = 0; mi < 4; mi++)
                #pragma unroll
                for (int ni = 0; ni < 8; ni++) {
                    const int bj = ni >> 1, sel = ni & 1;
                    mma_f16acc(acc[mi][ni], a[mi], b[bj][sel], b[bj][sel+2]);
                }
        }

        // release: one lane per warp arrives (all LDSMs for this stage done)
        if (l == 0) MBAR_ARRIVE(eb0 + (unsigned)stg * 8);

        // producer: thread 0 (after its own arrival) waits for all 8 warps,
        // then refills this slot with chunk s+2.
        if (tid == 0 && s + 2 < NITER) {
            mbar_wait(eb0 + (unsigned)stg * 8, par);
            issue(s + 2);
        }
    }

    // epilogue: fp32 combine + bias (+ residual)
    const int tr = l >> 2;
    const int tc = (l & 3) * 2;
    #pragma unroll
    for (int ni = 0; ni < 8; ni++) {
        const int col = n0 + wn*64 + ni*8 + tc;
        const float2 bv = *(const float2*)(bias + col);
        #pragma unroll
        for (int mi = 0; mi < 4; mi++) {
            const int row = m0 + wm*64 + mi*16 + tr;
            const float2 p0 = __half22float2(*(const __half2*)&acc[mi][ni][0]);
            const float2 p1 = __half22float2(*(const __half2*)&acc[mi][ni][1]);
            float x0 = p0.x + bv.x, y0 = p0.y + bv.y;
            float x1 = p1.x + bv.x, y1 = p1.y + bv.y;
            if (OUT_HALF) {
                __half2* C = (__half2*)Cout;
                C[((size_t)row     * N + col) >> 1] = __floats2half2_rn(x0, y0);
                C[((size_t)(row+8) * N + col) >> 1] = __floats2half2_rn(x1, y1);
            } else {
                float* C = (float*)Cout;
                const float2 r0 = *(const float2*)(res + (size_t)row * N + col);
                const float2 r1 = *(const float2*)(res + (size_t)(row+8) * N + col);
                *(float2*)(C + (size_t)row     * N + col) = make_float2(x0 + r0.x, y0 + r0.y);
                *(float2*)(C + (size_t)(row+8) * N + col) = make_float2(x1 + r1.x, y1 + r1.y);
            }
        }
    }
}

// ---------------- fused activation convert (grid-stride, both tensors) --------
__global__ __launch_bounds__(256)
void cvt_act2(const float4* __restrict__ x0, uint2* __restrict__ o0,
              const float4* __restrict__ x1, uint2* __restrict__ o1, int n4)
{
    const int stride = gridDim.x * 256;
    for (int i = blockIdx.x * 256 + threadIdx.x; i < n4; i += stride) {
        float4 v = x0[i];
        __half2 a = __floats2half2_rn(v.x, v.y);
        __half2 b = __floats2half2_rn(v.z, v.w);
        o0[i] = make_uint2(*(uint32_t*)&a, *(uint32_t*)&b);
        v = x1[i];
        a = __floats2half2_rn(v.x, v.y);
        b = __floats2half2_rn(v.z, v.w);
        o1[i] = make_uint2(*(uint32_t*)&a, *(uint32_t*)&b);
    }
}

// ---------------- fused weight transpose+convert (6 weights, one launch) ------
struct TW { const float* W; __half* T; int N; };
struct TW6 { TW t[6]; };

__global__ __launch_bounds__(256)
void transpose_all(TW6 p)
{
    const TW e = p.t[blockIdx.z];
    const int bx = blockIdx.x * 32;     // N offset
    if (bx >= e.N) return;
    const int by = blockIdx.y * 32;     // K offset
    __shared__ float t[32][33];
    const int tx = threadIdx.x & 31, ty = threadIdx.x >> 5;
    #pragma unroll
    for (int i = 0; i < 32; i += 8)
        t[ty + i][tx] = e.W[(size_t)(by + ty + i) * e.N + bx + tx];
    __syncthreads();
    #pragma unroll
    for (int i = 0; i < 32; i += 8)
        e.T[(size_t)(bx + ty + i) * KDIM + by + tx] = __float2half(t[tx][ty + i]);
}

// ---------------- bias concat ----------------
__global__ __launch_bounds__(256)
void concat_bias(const float* blq, const float* blkv, const float* bmq, const float* bmkv)
{
    const int i = blockIdx.x * 256 + threadIdx.x;   // 0..3071
    if (i < 1024) { g_bias_l[i] = blq[i];       g_bias_m[i] = bmq[i]; }
    else          { g_bias_l[i] = blkv[i-1024]; g_bias_m[i] = bmkv[i-1024]; }
}

// ---------------- per-token 8x8 cross-head attention: 2 tokens / block --------
// proj layout: [tok][3072] = [q(1024) | kv(2048)]
// mod0: q from pl, kv from pm ; mod1: q from pm, kv from pl
__global__ __launch_bounds__(256)
void attn_kernel()
{
    const int tok0 = blockIdx.x * 2;
    const int tid  = threadIdx.x;

    __shared__ __half sq [2][2][1024];
    __shared__ __half skv[2][2][8*264];
    __shared__ float  swt[2][2][8][8];

    {
        #pragma unroll
        for (int i = 0; i < 2; i++) {
            const int idx = tid + i*256;         // 0..511
            const int t = idx >> 8, rest = idx & 255;
            const int mod = rest >> 7, r = rest & 127;
            const __half* src = (mod ? g_pm : g_pl) + (size_t)(tok0 + t) * 3072;
            ((uint4*)sq[t][mod])[r] = ((const uint4*)src)[r];
        }
        #pragma unroll
        for (int i = 0; i < 4; i++) {
            const int idx = tid + i*256;         // 0..1023
            const int t = idx >> 9, rest = idx & 511;
            const int mod = rest >> 8, o8 = rest & 255;
            const int g = o8 >> 5, c = o8 & 31;
            const __half* src = (mod ? g_pl : g_pm) + (size_t)(tok0 + t) * 3072 + 1024;
            *(uint4*)&skv[t][mod][g*264 + c*8] = ((const uint4*)src)[o8];
        }
    }
    __syncthreads();

    {
        const int t = tid >> 7, mod = (tid >> 6) & 1, h = (tid >> 3) & 7, g = tid & 7;
        const __half2* q = (const __half2*)&sq [t][mod][h*128];
        const __half2* k = (const __half2*)&skv[t][mod][g*264];
        float s = 0.f;
        #pragma unroll
        for (int d = 0; d < 64; d++) {
            const float2 qf = __half22float2(q[d]);
            const float2 kf = __half22float2(k[d]);
            s += qf.x * kf.x + qf.y * kf.y;
        }
        swt[t][mod][h][g] = s * 0.08838834764831845f;   // 1/sqrt(128)
    }
    __syncthreads();

    if (tid < 32) {
        const int t = tid >> 4, mod = (tid >> 3) & 1, h = tid & 7;
        float mx = -1e30f;
        #pragma unroll
        for (int g = 0; g < 8; g++) mx = fmaxf(mx, swt[t][mod][h][g]);
        float e[8], sum = 0.f;
        #pragma unroll
        for (int g = 0; g < 8; g++) { e[g] = __expf(swt[t][mod][h][g] - mx); sum += e[g]; }
        const float inv = 1.0f / sum;
        #pragma unroll
        for (int g = 0; g < 8; g++) swt[t][mod][h][g] = e[g] * inv;
    }
    __syncthreads();

    #pragma unroll
    for (int j = 0; j < 2; j++) {
        const int idx = tid + j*256;
        const int t = idx >> 8, rest = idx & 255;
        const int mod = rest >> 7, h = (rest >> 4) & 7, db = (rest & 15) * 8;
        float o[8] = {0,0,0,0,0,0,0,0};
        #pragma unroll
        for (int g = 0; g < 8; g++) {
            const float wv = swt[t][mod][h][g];
            const __half2* v = (const __half2*)&skv[t][mod][g*264 + 128 + db];
            #pragma unroll
            for (int jj = 0; jj < 4; jj++) {
                const float2 vf = __half22float2(v[jj]);
                o[2*jj]   += wv * vf.x;
                o[2*jj+1] += wv * vf.y;
            }
        }
        __half hb[8];
        #pragma unroll
        for (int i = 0; i < 8; i++) hb[i] = __float2half(o[i]);
        __half* out = (mod == 0 ? g_al : g_am) + (size_t)(tok0 + t) * 1024 + h*128 + db;
        *(uint4*)out = *(uint4*)hb;
    }
}

// ---------------- launch ----------------
typedef CUresult (*EncFn)(CUtensorMap*, CUtensorMapDataType, cuuint32_t, void*,
                          const cuuint64_t*, const cuuint64_t*, const cuuint32_t*,
                          const cuuint32_t*, CUtensorMapInterleave, CUtensorMapSwizzle,
                          CUtensorMapL2promotion, CUtensorMapFloatOOBfill);

extern "C" void kernel_launch(void* const* d_in, const int* in_sizes, int n_in,
                              void* d_out, int out_size)
{
    (void)in_sizes; (void)n_in; (void)out_size;
    const float* liquid = (const float*)d_in[0];
    const float* mamba  = (const float*)d_in[1];
    const float* Wlq  = (const float*)d_in[2];
    const float* blq  = (const float*)d_in[3];
    const float* Wmkv = (const float*)d_in[4];
    const float* bmkv = (const float*)d_in[5];
    const float* Wmq  = (const float*)d_in[6];
    const float* bmq  = (const float*)d_in[7];
    const float* Wlkv = (const float*)d_in[8];
    const float* blkv = (const float*)d_in[9];
    const float* Wlo  = (const float*)d_in[10];
    const float* blo  = (const float*)d_in[11];
    const float* Wmo  = (const float*)d_in[12];
    const float* bmo  = (const float*)d_in[13];

    float* out_l = (float*)d_out;
    float* out_m = out_l + (size_t)NTOK * 1024;

    #define SYM(p, s) void* p; cudaGetSymbolAddress(&p, s)
    SYM(l16, g_l16); SYM(m16, g_m16);
    SYM(pl, g_pl);   SYM(pm, g_pm);
    SYM(al, g_al);   SYM(am, g_am);
    SYM(wl_cat, g_wl_cat); SYM(wm_cat, g_wm_cat);
    SYM(wlo, g_wlo); SYM(wmo, g_wmo);
    SYM(bias_l, g_bias_l); SYM(bias_m, g_bias_m);
    #undef SYM

    // driver entry point for tensor-map encoding (no libcuda link needed)
    void* enc_raw = nullptr;
    cudaDriverEntryPointQueryResult qres;
    cudaGetDriverEntryPointByVersion("cuTensorMapEncodeTiled", &enc_raw, 12000,
                                     cudaEnableDefault, &qres);
    EncFn enc = (EncFn)enc_raw;

    auto mk = [&](CUtensorMap* m, void* ptr, unsigned long long rows, unsigned box_rows) {
        cuuint64_t dims[2]    = {1024ull, rows};
        cuuint64_t strides[1] = {2048ull};          // row pitch in bytes
        cuuint32_t box[2]     = {64u, box_rows};    // 64 fp16 = 128B (SW128 atom)
        cuuint32_t es[2]      = {1u, 1u};
        enc(m, CU_TENSOR_MAP_DATA_TYPE_FLOAT16, 2, ptr, dims, strides, box, es,
            CU_TENSOR_MAP_INTERLEAVE_NONE, CU_TENSOR_MAP_SWIZZLE_128B,
            CU_TENSOR_MAP_L2_PROMOTION_L2_128B, CU_TENSOR_MAP_FLOAT_OOB_FILL_NONE);
    };

    cudaFuncSetAttribute(gemm_f16<true>,  cudaFuncAttributeMaxDynamicSharedMemorySize, DSMEM_BYTES);
    cudaFuncSetAttribute(gemm_f16<false>, cudaFuncAttributeMaxDynamicSharedMemorySize, DSMEM_BYTES);

    // stage 0: fused prep
    cvt_act2<<<2048, 256>>>((const float4*)liquid, (uint2*)l16,
                            (const float4*)mamba,  (uint2*)m16, NTOK*1024/4);
    TW6 tw;
    tw.t[0] = {Wlq,  (__half*)wl_cat,                      1024};
    tw.t[1] = {Wlkv, (__half*)wl_cat + (size_t)1024*KDIM,  2048};
    tw.t[2] = {Wmq,  (__half*)wm_cat,                      1024};
    tw.t[3] = {Wmkv, (__half*)wm_cat + (size_t)1024*KDIM,  2048};
    tw.t[4] = {Wlo,  (__half*)wlo,                         1024};
    tw.t[5] = {Wmo,  (__half*)wmo,                         1024};
    transpose_all<<<dim3(64, 32, 6), 256>>>(tw);
    concat_bias<<<12, 256>>>(blq, blkv, bmq, bmkv);

    // stage 1: fused q|kv projections, both modalities in ONE launch (grid.z=2)
    const int gm = NTOK / BM;  // 256
    {
        TMaps maps;
        mk(&maps.a[0], l16, NTOK, 128);      mk(&maps.a[1], m16, NTOK, 128);
        mk(&maps.b[0], wl_cat, 3072, 256);   mk(&maps.b[1], wm_cat, 3072, 256);
        GPair p;
        p.bias[0] = (const float*)bias_l; p.bias[1] = (const float*)bias_m;
        p.res[0] = nullptr;               p.res[1] = nullptr;
        p.C[0]  = pl;                     p.C[1]  = pm;
        gemm_f16<true><<<dim3(gm * (3072/BN), 1, 2), 256, DSMEM_BYTES>>>(maps, p, 3072, 3072/BN);
    }

    // stage 2: per-token attention (2 tokens per block)
    attn_kernel<<<NTOK/2, 256>>>();

    // stage 3: output projections + residual, both modalities in ONE launch
    {
        TMaps maps;
        mk(&maps.a[0], al, NTOK, 128);    mk(&maps.a[1], am, NTOK, 128);
        mk(&maps.b[0], wlo, 1024, 256);   mk(&maps.b[1], wmo, 1024, 256);
        GPair p;
        p.bias[0] = blo;   p.bias[1] = bmo;
        p.res[0] = liquid; p.res[1] = mamba;
        p.C[0]  = out_l;   p.C[1]  = out_m;
        gemm_f16<false><<<dim3(gm * (1024/BN), 1, 2), 256, DSMEM_BYTES>>>(maps, p, 1024, 1024/BN);
    }
}